// round 2
// baseline (speedup 1.0000x reference)
#include <cuda_runtime.h>
#include <math.h>
#include <stdint.h>

typedef unsigned long long u64;

#define BB 16
#define DD 512
#define HW 484
#define LE 1452
#define LDQ 484
#define TEMPF 30.0f
#define NSCALE 0.011048543456039806f
#define DHWF 247808.0f
#define IEPS 1e-5f
#define GRP 247808

// ---- scratch layout (floats) ----
#define OFF_PE    ((size_t)0)
#define SZ_PE     ((size_t)HW*DD)
#define OFF_LABEL (OFF_PE + SZ_PE)
#define SZ_LABEL  ((size_t)BB*LE)
#define OFF_XE    (OFF_LABEL + SZ_LABEL)
#define SZ_XE     ((size_t)BB*LE*DD)
#define OFF_X1E   (OFF_XE + SZ_XE)
#define OFF_MEM   (OFF_X1E + SZ_XE)
#define OFF_PQ    (OFF_MEM + SZ_XE)
#define SZ_PQ     ((size_t)BB*LE*128)
#define OFF_PKC   (OFF_PQ + SZ_PQ)
#define OFF_DX0   (OFF_PKC + SZ_PQ)
#define SZ_DX     ((size_t)96*LDQ*DD)
#define OFF_DX1   (OFF_DX0 + SZ_DX)
#define OFF_DX    (OFF_DX1 + SZ_DX)
#define OFF_DXPT3 (OFF_DX + SZ_DX)
#define OFF_DPQ   (OFF_DXPT3 + SZ_DX)
#define SZ_DPQ    ((size_t)96*LDQ*128)
#define OFF_DMASK (OFF_DPQ + SZ_DPQ)
#define SZ_DMASK  ((size_t)96*LDQ)
#define OFF_DSC   (OFF_DMASK + SZ_DMASK)
#define SZ_DSC    ((size_t)96*4)
#define SCRATCH_TOTAL (OFF_DSC + SZ_DSC)

__device__ __align__(16) float g_scratch[SCRATCH_TOTAL];

// ---- f32x2 helpers ----
__device__ __forceinline__ u64 ffma2(u64 a, u64 b, u64 c) {
    u64 d;
    asm("fma.rn.f32x2 %0, %1, %2, %3;" : "=l"(d) : "l"(a), "l"(b), "l"(c));
    return d;
}
__device__ __forceinline__ u64 pack2(float lo, float hi) {
    u64 r;
    asm("mov.b64 %0, {%1, %2};" : "=l"(r) : "f"(lo), "f"(hi));
    return r;
}
__device__ __forceinline__ void unpack2(u64 v, float& lo, float& hi) {
    asm("mov.b64 {%0, %1}, %2;" : "=f"(lo), "=f"(hi) : "l"(v));
}
__device__ __forceinline__ float hsum2(u64 v) {
    float a, b;
    unpack2(v, a, b);
    return a + b;
}

// ---- 1. sinusoidal position embedding pe[p][c], p=0..483, c=0..511 ----
__global__ void pe_kernel(float* __restrict__ pe) {
    int idx = blockIdx.x * 256 + threadIdx.x;
    if (idx >= HW * DD) return;
    int p = idx >> 9, c = idx & 511;
    float pos = (float)(p + 1);
    int j = c & 255;
    float f = powf(10000.0f, -(float)j * (1.0f / 256.0f));
    float a = pos * f;
    pe[idx] = (c < 256) ? sinf(a) : cosf(a);
}

// ---- 2. label gather: (ni,b,hw) -> [b][ni*hw+p] ----
__global__ void label_kernel(const float* __restrict__ lab, float* __restrict__ out) {
    int idx = blockIdx.x * 256 + threadIdx.x;
    if (idx >= 3 * BB * HW) return;
    int p = idx % HW;
    int t = idx / HW;
    int b = t % BB;
    int ni = t / BB;
    out[(size_t)b * LE + ni * HW + p] = lab[idx];
}

// ---- 3. x = flatten(feat) + pe*1e-3 (d,hw transpose) ----
// mode 0: row = b*LE + img*HW + p ; mode 1: row = g*LDQ + p
__global__ void build_kernel(const float* __restrict__ fa, const float* __restrict__ fb,
                             int split, const float* __restrict__ pe,
                             float* __restrict__ xout, int mode) {
    int g = blockIdx.x;
    int img = g >> 4, b = g & 15;
    const float* f = (img < split) ? (fa + (size_t)img * BB * DD * HW)
                                   : (fb + (size_t)(img - split) * BB * DD * HW);
    int p0 = blockIdx.y * 32, c0 = blockIdx.z * 32;
    __shared__ float t[32][33];
    int tx = threadIdx.x, ty = threadIdx.y;
#pragma unroll
    for (int r = 0; r < 4; r++) {
        int c = c0 + ty + r * 8, p = p0 + tx;
        if (p < HW) t[ty + r * 8][tx] = f[((size_t)b * DD + c) * HW + p];
    }
    __syncthreads();
#pragma unroll
    for (int r = 0; r < 4; r++) {
        int p = p0 + ty + r * 8, c = c0 + tx;
        if (p < HW) {
            size_t row = (mode == 0) ? ((size_t)b * LE + (size_t)img * HW + p)
                                     : ((size_t)g * LDQ + p);
            xout[row * DD + c] = t[tx][ty + r * 8] + pe[(size_t)p * DD + c] * 1e-3f;
        }
    }
}

// ---- 4. projection + L2 normalize: PQ = normalize(X@WK^T + BK), f32x2 ----
__global__ void __launch_bounds__(256) proj_kernel(const float* __restrict__ X,
                                                   const float* __restrict__ WK,
                                                   const float* __restrict__ BK,
                                                   float* __restrict__ PQ, int L) {
    extern __shared__ float sm[];
    float* WS = sm;               // [128][132], WS[c][i] = WK[c][kc+i]
    float* XT = sm + 128 * 132;   // [16][128]
    float* O  = sm;               // alias WS after mainloop: [16][132]
    __shared__ float rnorm[16];
    int g = blockIdx.x, l0 = blockIdx.y * 16, t = threadIdx.x;
    int c = t & 127, half = t >> 7;
    u64 acc[8];
#pragma unroll
    for (int r = 0; r < 8; r++) acc[r] = 0ull;

    for (int kc = 0; kc < 512; kc += 128) {
#pragma unroll 4
        for (int j = 0; j < 64; j++) {
            int flat = j * 256 + t;
            int cc = flat >> 7, ii = flat & 127;
            WS[cc * 132 + ii] = WK[(size_t)cc * 512 + kc + ii];
        }
#pragma unroll
        for (int j = 0; j < 8; j++) {
            int flat = j * 256 + t;
            int rr = flat >> 7, ii = flat & 127;
            int l = l0 + rr;
            XT[rr * 128 + ii] = (l < L) ? X[((size_t)g * L + l) * 512 + kc + ii] : 0.0f;
        }
        __syncthreads();
#pragma unroll 8
        for (int i = 0; i < 128; i += 4) {
            ulonglong2 wv = *(const ulonglong2*)(WS + c * 132 + i);
#pragma unroll
            for (int r8 = 0; r8 < 8; r8++) {
                ulonglong2 xv = *(const ulonglong2*)(XT + (half * 8 + r8) * 128 + i);
                acc[r8] = ffma2(wv.x, xv.x, acc[r8]);
                acc[r8] = ffma2(wv.y, xv.y, acc[r8]);
            }
        }
        __syncthreads();
    }
    float bias = BK[c];
#pragma unroll
    for (int r8 = 0; r8 < 8; r8++) O[(half * 8 + r8) * 132 + c] = hsum2(acc[r8]) + bias;
    __syncthreads();
    int w = t >> 5, lane = t & 31;
    for (int rr = w * 2; rr < w * 2 + 2; rr++) {
        float s = 0.0f;
#pragma unroll
        for (int q = 0; q < 4; q++) {
            float v = O[rr * 132 + lane + q * 32];
            s += v * v;
        }
#pragma unroll
        for (int m = 16; m; m >>= 1) s += __shfl_xor_sync(0xffffffffu, s, m);
        if (lane == 0) rnorm[rr] = 1.0f / fmaxf(sqrtf(s), 1e-12f);
    }
    __syncthreads();
#pragma unroll
    for (int r8 = 0; r8 < 8; r8++) {
        int rr = half * 8 + r8;
        int l = l0 + rr;
        if (l < L) PQ[((size_t)g * L + l) * 128 + c] = O[rr * 132 + c] * rnorm[rr];
    }
}

// ---- 5. attention (self, or fused cross with label) ----
// OUT[g][q] = RES[g][q] + sum_k a_qk*(label_k)*V[gk][k]; mask out if LABEL.
__global__ void __launch_bounds__(256) attn_kernel(const float* __restrict__ PQ,
                                                   const float* __restrict__ PK,
                                                   const float* __restrict__ V,
                                                   const float* __restrict__ RES,
                                                   float* __restrict__ OUT,
                                                   const float* __restrict__ LABEL,
                                                   float* __restrict__ MASKOUT,
                                                   int Lq, int Lk, int pkMod) {
    extern __shared__ float sm[];
    float* qv = sm;           // [16][132]
    float* P  = sm + 2112;    // [Lk][20]
    int g = blockIdx.x;
    int gk = pkMod ? (g & 15) : g;
    int q0 = blockIdx.y * 16;
    int t = threadIdx.x;

    // phase 1: q tile to smem
#pragma unroll
    for (int j = 0; j < 8; j++) {
        int flat = j * 256 + t;
        int r = flat >> 7, i = flat & 127;
        int l = q0 + r;
        qv[r * 132 + i] = (l < Lq) ? PQ[((size_t)g * Lq + l) * 128 + i] : 0.0f;
    }
    __syncthreads();

    // phase 2: logits, 4k x 4q register tiles
    for (int tau = t; tau < Lk; tau += 256) {
        int k0 = (tau >> 2) * 4;
        int qg = (tau & 3) * 4;
        const float* pk0 = PK + ((size_t)gk * Lk + k0) * 128;
        u64 acc[4][4];
#pragma unroll
        for (int a = 0; a < 4; a++)
#pragma unroll
            for (int b = 0; b < 4; b++) acc[a][b] = 0ull;
#pragma unroll 4
        for (int i = 0; i < 128; i += 4) {
            ulonglong2 kv[4], qq[4];
#pragma unroll
            for (int kj = 0; kj < 4; kj++) kv[kj] = *(const ulonglong2*)(pk0 + kj * 128 + i);
#pragma unroll
            for (int qj = 0; qj < 4; qj++) qq[qj] = *(const ulonglong2*)(qv + (qg + qj) * 132 + i);
#pragma unroll
            for (int kj = 0; kj < 4; kj++)
#pragma unroll
                for (int qj = 0; qj < 4; qj++) {
                    acc[kj][qj] = ffma2(kv[kj].x, qq[qj].x, acc[kj][qj]);
                    acc[kj][qj] = ffma2(kv[kj].y, qq[qj].y, acc[kj][qj]);
                }
        }
#pragma unroll
        for (int kj = 0; kj < 4; kj++)
#pragma unroll
            for (int qj = 0; qj < 4; qj++)
                P[(k0 + kj) * 20 + qg + qj] = hsum2(acc[kj][qj]) * TEMPF;
    }
    __syncthreads();

    // phase 3: softmax per q row; fold 1/sum (and label) into P
    {
        int w = t >> 5, lane = t & 31;
        for (int r = w * 2; r < w * 2 + 2; r++) {
            if (q0 + r >= Lq) continue;
            float mx = -1e30f;
            for (int k = lane; k < Lk; k += 32) mx = fmaxf(mx, P[k * 20 + r]);
#pragma unroll
            for (int m = 16; m; m >>= 1) mx = fmaxf(mx, __shfl_xor_sync(0xffffffffu, mx, m));
            float sum = 0.0f;
            for (int k = lane; k < Lk; k += 32) {
                float e = __expf(P[k * 20 + r] - mx);
                P[k * 20 + r] = e;
                sum += e;
            }
#pragma unroll
            for (int m = 16; m; m >>= 1) sum += __shfl_xor_sync(0xffffffffu, sum, m);
            float rinv = 1.0f / sum;
            if (LABEL) {
                const float* lb = LABEL + (size_t)gk * Lk;
                float ms = 0.0f;
                for (int k = lane; k < Lk; k += 32) {
                    float pv = P[k * 20 + r] * rinv * lb[k];
                    P[k * 20 + r] = pv;
                    ms += pv;
                }
#pragma unroll
                for (int m = 16; m; m >>= 1) ms += __shfl_xor_sync(0xffffffffu, ms, m);
                if (lane == 0) MASKOUT[(size_t)g * Lq + q0 + r] = ms;
            } else {
                for (int k = lane; k < Lk; k += 32) P[k * 20 + r] *= rinv;
            }
        }
    }
    __syncthreads();

    // phase 4: value accumulation; thread = 4 d x 8 q (4 packed q-pairs)
    int dq = t & 127, qh = t >> 7;
    int d0 = dq * 4, qb = qh * 8;
    u64 acc[4][4];  // [di][qpair], halves = (row, row+1)
#pragma unroll
    for (int qp = 0; qp < 4; qp++) {
        int l0 = q0 + qb + 2 * qp;
        float4 r0 = make_float4(0.f, 0.f, 0.f, 0.f), r1 = r0;
        if (l0 < Lq)     r0 = *(const float4*)(RES + ((size_t)g * Lq + l0) * 512 + d0);
        if (l0 + 1 < Lq) r1 = *(const float4*)(RES + ((size_t)g * Lq + l0 + 1) * 512 + d0);
        acc[0][qp] = pack2(r0.x, r1.x);
        acc[1][qp] = pack2(r0.y, r1.y);
        acc[2][qp] = pack2(r0.z, r1.z);
        acc[3][qp] = pack2(r0.w, r1.w);
    }
    const float* vb = V + (size_t)gk * Lk * 512 + d0;
    const float* pb = P + qb;
#pragma unroll 2
    for (int k = 0; k < Lk; k++) {
        float4 v4 = *(const float4*)(vb + (size_t)k * 512);
        ulonglong2 wA = *(const ulonglong2*)(pb + k * 20);      // pairs (q0,q1),(q2,q3)
        ulonglong2 wB = *(const ulonglong2*)(pb + k * 20 + 4);  // pairs (q4,q5),(q6,q7)
        u64 v0 = pack2(v4.x, v4.x), v1 = pack2(v4.y, v4.y);
        u64 v2 = pack2(v4.z, v4.z), v3 = pack2(v4.w, v4.w);
        acc[0][0] = ffma2(wA.x, v0, acc[0][0]);
        acc[1][0] = ffma2(wA.x, v1, acc[1][0]);
        acc[2][0] = ffma2(wA.x, v2, acc[2][0]);
        acc[3][0] = ffma2(wA.x, v3, acc[3][0]);
        acc[0][1] = ffma2(wA.y, v0, acc[0][1]);
        acc[1][1] = ffma2(wA.y, v1, acc[1][1]);
        acc[2][1] = ffma2(wA.y, v2, acc[2][1]);
        acc[3][1] = ffma2(wA.y, v3, acc[3][1]);
        acc[0][2] = ffma2(wB.x, v0, acc[0][2]);
        acc[1][2] = ffma2(wB.x, v1, acc[1][2]);
        acc[2][2] = ffma2(wB.x, v2, acc[2][2]);
        acc[3][2] = ffma2(wB.x, v3, acc[3][2]);
        acc[0][3] = ffma2(wB.y, v0, acc[0][3]);
        acc[1][3] = ffma2(wB.y, v1, acc[1][3]);
        acc[2][3] = ffma2(wB.y, v2, acc[2][3]);
        acc[3][3] = ffma2(wB.y, v3, acc[3][3]);
    }
#pragma unroll
    for (int qp = 0; qp < 4; qp++) {
        int l0 = q0 + qb + 2 * qp;
        float lo0, hi0, lo1, hi1, lo2, hi2, lo3, hi3;
        unpack2(acc[0][qp], lo0, hi0);
        unpack2(acc[1][qp], lo1, hi1);
        unpack2(acc[2][qp], lo2, hi2);
        unpack2(acc[3][qp], lo3, hi3);
        if (l0 < Lq)
            *(float4*)(OUT + ((size_t)g * Lq + l0) * 512 + d0) = make_float4(lo0, lo1, lo2, lo3);
        if (l0 + 1 < Lq)
            *(float4*)(OUT + ((size_t)g * Lq + l0 + 1) * 512 + d0) = make_float4(hi0, hi1, hi2, hi3);
    }
}

// ---- 6. InstanceL2Norm over contiguous groups of 247808 ----
__global__ void inorm_kernel(const float* __restrict__ in, float* __restrict__ out) {
    size_t base = (size_t)blockIdx.x * GRP;
    int t = threadIdx.x;
    const float4* ip = (const float4*)(in + base);
    float ss = 0.0f;
    for (int i = t; i < GRP / 4; i += 256) {
        float4 v = ip[i];
        ss += v.x * v.x + v.y * v.y + v.z * v.z + v.w * v.w;
    }
    __shared__ float red[8];
    __shared__ float scs;
#pragma unroll
    for (int m = 16; m; m >>= 1) ss += __shfl_xor_sync(0xffffffffu, ss, m);
    if ((t & 31) == 0) red[t >> 5] = ss;
    __syncthreads();
    if (t == 0) {
        float s = 0.0f;
#pragma unroll
        for (int i = 0; i < 8; i++) s += red[i];
        scs = NSCALE * sqrtf(DHWF / (s + IEPS));
    }
    __syncthreads();
    float scale = scs;
    float4* op = (float4*)(out + base);
    for (int i = t; i < GRP / 4; i += 256) {
        float4 v = ip[i];
        v.x *= scale; v.y *= scale; v.z *= scale; v.w *= scale;
        op[i] = v;
    }
}

// ---- 7. decoder 3-sum reduction: u=x*mask, v=x+t3 ----
__global__ void dec_reduce_kernel(const float* __restrict__ X, const float* __restrict__ XP,
                                  const float* __restrict__ MASK, float* __restrict__ SC) {
    int g = blockIdx.x;
    size_t base = (size_t)g * GRP;
    __shared__ float mk[LDQ];
    int t = threadIdx.x;
    for (int i = t; i < LDQ; i += 256) mk[i] = MASK[(size_t)g * LDQ + i];
    __syncthreads();
    const float4* xp4 = (const float4*)(X + base);
    const float4* pp4 = (const float4*)(XP + base);
    float s2 = 0.0f, s4 = 0.0f, cr = 0.0f;
    for (int i = t; i < GRP / 4; i += 256) {
        float m = mk[i >> 7];
        float4 x = xp4[i];
        float4 v = pp4[i];
        float ux = x.x * m, uy = x.y * m, uz = x.z * m, uw = x.w * m;
        s2 += ux * ux + uy * uy + uz * uz + uw * uw;
        s4 += v.x * v.x + v.y * v.y + v.z * v.z + v.w * v.w;
        cr += ux * v.x + uy * v.y + uz * v.z + uw * v.w;
    }
    __shared__ float r2[8], r4[8], rc[8];
#pragma unroll
    for (int m = 16; m; m >>= 1) {
        s2 += __shfl_xor_sync(0xffffffffu, s2, m);
        s4 += __shfl_xor_sync(0xffffffffu, s4, m);
        cr += __shfl_xor_sync(0xffffffffu, cr, m);
    }
    if ((t & 31) == 0) { r2[t >> 5] = s2; r4[t >> 5] = s4; rc[t >> 5] = cr; }
    __syncthreads();
    if (t == 0) {
        float a = 0.0f, b = 0.0f, c = 0.0f;
#pragma unroll
        for (int i = 0; i < 8; i++) { a += r2[i]; b += r4[i]; c += rc[i]; }
        float S2 = NSCALE * sqrtf(DHWF / (a + IEPS));
        float S4 = NSCALE * sqrtf(DHWF / (b + IEPS));
        float sso = S2 * S2 * a + 2.0f * S2 * S4 * c + S4 * S4 * b;
        float SO = NSCALE * sqrtf(DHWF / (sso + IEPS));
        SC[g * 4 + 0] = S2;
        SC[g * 4 + 1] = S4;
        SC[g * 4 + 2] = SO;
    }
}

// ---- 8. final combine + transpose write ----
__global__ void final_kernel(const float* __restrict__ X, const float* __restrict__ XP,
                             const float* __restrict__ MASK, const float* __restrict__ SC,
                             float* __restrict__ out) {
    int g = blockIdx.x;
    float S2 = SC[g * 4 + 0], S4 = SC[g * 4 + 1], SO = SC[g * 4 + 2];
    int p0 = blockIdx.y * 32, c0 = blockIdx.z * 32;
    __shared__ float tile[32][33];
    int tx = threadIdx.x, ty = threadIdx.y;
    size_t base = (size_t)g * GRP;
#pragma unroll
    for (int r = 0; r < 4; r++) {
        int p = p0 + ty + r * 8, c = c0 + tx;
        if (p < LDQ) {
            size_t idx = base + (size_t)p * 512 + c;
            float u = X[idx] * MASK[(size_t)g * LDQ + p];
            tile[ty + r * 8][tx] = SO * (S2 * u + S4 * XP[idx]);
        }
    }
    __syncthreads();
#pragma unroll
    for (int r = 0; r < 4; r++) {
        int p = p0 + tx, c = c0 + ty + r * 8;
        if (p < LDQ) out[((size_t)g * 512 + c) * LDQ + p] = tile[tx][ty + r * 8];
    }
}

// ---- launcher ----
extern "C" void kernel_launch(void* const* d_in, const int* in_sizes, int n_in,
                              void* d_out, int out_size) {
    const float* train_feat  = (const float*)d_in[0];
    const float* test_feat   = (const float*)d_in[1];
    const float* train_label = (const float*)d_in[2];
    const float* wk_self     = (const float*)d_in[3];
    const float* bk_self     = (const float*)d_in[4];
    const float* wk_cross    = (const float*)d_in[5];
    const float* bk_cross    = (const float*)d_in[6];
    float* out = (float*)d_out;

    const int SM_BIG   = (2112 + LE * 20) * 4;    // 124608
    const int SM_SMALL = (2112 + LDQ * 20) * 4;   // 46848
    const int SM_PROJ  = (128 * 132 + 16 * 128) * 4;  // 75776
    cudaFuncSetAttribute(attn_kernel, cudaFuncAttributeMaxDynamicSharedMemorySize, SM_BIG);
    cudaFuncSetAttribute(proj_kernel, cudaFuncAttributeMaxDynamicSharedMemorySize, SM_PROJ);

    float* base = nullptr;
    cudaGetSymbolAddress((void**)&base, g_scratch);
    float* pe    = base + OFF_PE;
    float* label = base + OFF_LABEL;
    float* xe    = base + OFF_XE;
    float* x1e   = base + OFF_X1E;
    float* mem   = base + OFF_MEM;
    float* pq    = base + OFF_PQ;
    float* pkc   = base + OFF_PKC;
    float* dx0   = base + OFF_DX0;
    float* dx1   = base + OFF_DX1;
    float* dx    = base + OFF_DX;
    float* dxpt3 = base + OFF_DXPT3;
    float* dpq   = base + OFF_DPQ;
    float* dmask = base + OFF_DMASK;
    float* dsc   = base + OFF_DSC;

    dim3 tb(32, 8);

    pe_kernel<<<(HW * DD + 255) / 256, 256>>>(pe);
    label_kernel<<<(3 * BB * HW + 255) / 256, 256>>>(train_label, label);

    // encoder
    build_kernel<<<dim3(48, 16, 16), tb>>>(train_feat, train_feat, 3, pe, xe, 0);
    proj_kernel<<<dim3(16, 91), 256, SM_PROJ>>>(xe, wk_self, bk_self, pq, LE);
    attn_kernel<<<dim3(16, 91), 256, SM_BIG>>>(pq, pq, xe, xe, x1e, nullptr, nullptr, LE, LE, 0);
    inorm_kernel<<<48, 256>>>(x1e, mem);
    proj_kernel<<<dim3(16, 91), 256, SM_PROJ>>>(mem, wk_cross, bk_cross, pkc, LE);

    // decoder (all 6 images batched: g = img*16 + b)
    build_kernel<<<dim3(96, 16, 16), tb>>>(train_feat, test_feat, 3, pe, dx0, 1);
    proj_kernel<<<dim3(96, 31), 256, SM_PROJ>>>(dx0, wk_self, bk_self, dpq, LDQ);
    attn_kernel<<<dim3(96, 31), 256, SM_SMALL>>>(dpq, dpq, dx0, dx0, dx1, nullptr, nullptr,
                                                 LDQ, LDQ, 0);
    inorm_kernel<<<96, 256>>>(dx1, dx);
    proj_kernel<<<dim3(96, 31), 256, SM_PROJ>>>(dx, wk_cross, bk_cross, dpq, LDQ);
    attn_kernel<<<dim3(96, 31), 256, SM_BIG>>>(dpq, pkc, mem, dx, dxpt3, label, dmask,
                                               LDQ, LE, 1);
    dec_reduce_kernel<<<96, 256>>>(dx, dxpt3, dmask, dsc);
    final_kernel<<<dim3(96, 16, 16), tb>>>(dx, dxpt3, dmask, dsc, out);
}

// round 3
// speedup vs baseline: 2.0985x; 2.0985x over previous
#include <cuda_runtime.h>
#include <math.h>
#include <stdint.h>

typedef unsigned long long u64;

#define BB 16
#define DD 512
#define HW 484
#define LE 1452
#define LDQ 484
#define NSCALE 0.011048543456039806f
#define DHWF 247808.0f
#define IEPS 1e-5f
#define GRP 247808
#define QF4 15488   // GRP/4/4 : float4s per quarter

// ---- scratch layout (floats) ----
#define SZ_PE     ((size_t)HW*DD)
#define SZ_LABEL  ((size_t)BB*LE)
#define SZ_XE     ((size_t)BB*LE*DD)
#define SZ_PQ     ((size_t)BB*LE*128)
#define SZ_DX     ((size_t)96*LDQ*DD)
#define SZ_DPQ    ((size_t)96*LDQ*128)
#define SZ_DMASK  ((size_t)96*LDQ)
#define SZ_PROBS  ((size_t)96*LDQ*1456)

#define OFF_PE    ((size_t)0)
#define OFF_LABEL (OFF_PE + SZ_PE)
#define OFF_XE    (OFF_LABEL + SZ_LABEL)
#define OFF_X1E   (OFF_XE + SZ_XE)
#define OFF_MEM   (OFF_X1E + SZ_XE)
#define OFF_PQ    (OFF_MEM + SZ_XE)
#define OFF_PKC   (OFF_PQ + SZ_PQ)
#define OFF_DX0   (OFF_PKC + SZ_PQ)
#define OFF_DX1   (OFF_DX0 + SZ_DX)
#define OFF_DX    (OFF_DX1 + SZ_DX)
#define OFF_DXPT3 (OFF_DX + SZ_DX)
#define OFF_DPQ   (OFF_DXPT3 + SZ_DX)
#define OFF_DMASK (OFF_DPQ + SZ_DPQ)
#define OFF_DSC   (OFF_DMASK + SZ_DMASK)
#define OFF_IPART (OFF_DSC + 96*4)
#define OFF_DPART (OFF_IPART + 96*4)
#define OFF_PROBS (OFF_DPART + 96*4*3)
#define SCRATCH_TOTAL (OFF_PROBS + SZ_PROBS)

__device__ __align__(16) float g_scratch[SCRATCH_TOTAL];

// ---- f32x2 helpers ----
__device__ __forceinline__ u64 ffma2(u64 a, u64 b, u64 c) {
    u64 d;
    asm("fma.rn.f32x2 %0, %1, %2, %3;" : "=l"(d) : "l"(a), "l"(b), "l"(c));
    return d;
}
__device__ __forceinline__ u64 pack2(float lo, float hi) {
    u64 r;
    asm("mov.b64 %0, {%1, %2};" : "=l"(r) : "f"(lo), "f"(hi));
    return r;
}
__device__ __forceinline__ void unpack2(u64 v, float& lo, float& hi) {
    asm("mov.b64 {%0, %1}, %2;" : "=f"(lo), "=f"(hi) : "l"(v));
}

__device__ __forceinline__ void ld8(const float* p, bool valid, float* r) {
    if (valid) {
        float4 v0 = *(const float4*)p;
        float4 v1 = *(const float4*)(p + 4);
        r[0] = v0.x; r[1] = v0.y; r[2] = v0.z; r[3] = v0.w;
        r[4] = v1.x; r[5] = v1.y; r[6] = v1.z; r[7] = v1.w;
    } else {
#pragma unroll
        for (int j = 0; j < 8; j++) r[j] = 0.0f;
    }
}

// ================= generic batched GEMM =================
// C[g] = alpha * A[g] @ op(B[gk]) (+ Cin[g]);  op = B^T if TRANSB (B is [N][K])
template<int TRANSB>
__global__ void __launch_bounds__(256, 2)
gemm_kernel(const float* __restrict__ A, const float* __restrict__ B,
            const float* __restrict__ Cin, float* __restrict__ C,
            int M, int N, int Kloop, int KB,
            int ldA, int ldB, int ldC,
            size_t sA, size_t sB, size_t sC,
            int gkMod, float alpha, int addC) {
    __shared__ float As[16][132];
    __shared__ float Bs[16][132];
    int g = blockIdx.z;
    int gk = gkMod ? (g & 15) : g;
    const float* Ag = A + (size_t)g * sA;
    const float* Bg = B + (size_t)gk * sB;
    int mBase = blockIdx.y * 128, nBase = blockIdx.x * 128;
    int t = threadIdx.x;

    int am = t >> 1, ak = (t & 1) * 8;
    bool avalid = (mBase + am) < M;
    const float* aPtr = Ag + (size_t)(mBase + am) * ldA + ak;

    int bn = t >> 1, bk = (t & 1) * 8;       // TRANSB path
    int bk2 = t >> 4, bnq = (t & 15) * 8;    // NN path
    bool bnvalid = (nBase + bn) < N;
    const float* bPtrT = Bg + (size_t)(nBase + bn) * ldB + bk;
    const float* bPtrN = Bg + (size_t)bk2 * ldB + nBase + bnq;

    float ra[8], rb[8];
    ld8(aPtr, avalid, ra);
    if (TRANSB) ld8(bPtrT, bnvalid, rb);
    else        ld8(bPtrN, bk2 < KB, rb);

    u64 acc[8][4];
#pragma unroll
    for (int i = 0; i < 8; i++)
#pragma unroll
        for (int j = 0; j < 4; j++) acc[i][j] = 0ull;

    int m0 = (t >> 4) * 8, n0 = (t & 15) * 8;

    for (int k0 = 0; k0 < Kloop; k0 += 16) {
        __syncthreads();
#pragma unroll
        for (int j = 0; j < 8; j++) As[ak + j][am] = ra[j];
        if (TRANSB) {
#pragma unroll
            for (int j = 0; j < 8; j++) Bs[bk + j][bn] = rb[j];
        } else {
            *(float4*)&Bs[bk2][bnq]     = make_float4(rb[0], rb[1], rb[2], rb[3]);
            *(float4*)&Bs[bk2][bnq + 4] = make_float4(rb[4], rb[5], rb[6], rb[7]);
        }
        __syncthreads();
        int kn = k0 + 16;
        if (kn < Kloop) {
            ld8(aPtr + kn, avalid, ra);
            if (TRANSB) ld8(bPtrT + kn, bnvalid, rb);
            else        ld8(bPtrN + (size_t)kn * ldB, (kn + bk2) < KB, rb);
        }
#pragma unroll
        for (int kk = 0; kk < 16; kk++) {
            ulonglong2 bA = *(const ulonglong2*)&Bs[kk][n0];
            ulonglong2 bBv = *(const ulonglong2*)&Bs[kk][n0 + 4];
            float4 a0 = *(const float4*)&As[kk][m0];
            float4 a1 = *(const float4*)&As[kk][m0 + 4];
            float av[8] = {a0.x, a0.y, a0.z, a0.w, a1.x, a1.y, a1.z, a1.w};
#pragma unroll
            for (int i = 0; i < 8; i++) {
                u64 ad = pack2(av[i], av[i]);
                acc[i][0] = ffma2(ad, bA.x, acc[i][0]);
                acc[i][1] = ffma2(ad, bA.y, acc[i][1]);
                acc[i][2] = ffma2(ad, bBv.x, acc[i][2]);
                acc[i][3] = ffma2(ad, bBv.y, acc[i][3]);
            }
        }
    }

    bool fullN = (nBase + 128) <= N;
#pragma unroll
    for (int i = 0; i < 8; i++) {
        int m = mBase + m0 + i;
        if (m >= M) continue;
        float o[8];
#pragma unroll
        for (int j = 0; j < 4; j++) unpack2(acc[i][j], o[2 * j], o[2 * j + 1]);
#pragma unroll
        for (int j = 0; j < 8; j++) o[j] *= alpha;
        size_t off = (size_t)g * sC + (size_t)m * ldC + nBase + n0;
        if (fullN) {
            if (addC) {
                float4 c0 = *(const float4*)(Cin + off);
                float4 c1 = *(const float4*)(Cin + off + 4);
                o[0] += c0.x; o[1] += c0.y; o[2] += c0.z; o[3] += c0.w;
                o[4] += c1.x; o[5] += c1.y; o[6] += c1.z; o[7] += c1.w;
            }
            *(float4*)(C + off)     = make_float4(o[0], o[1], o[2], o[3]);
            *(float4*)(C + off + 4) = make_float4(o[4], o[5], o[6], o[7]);
        } else {
#pragma unroll
            for (int j = 0; j < 8; j++) {
                int n = nBase + n0 + j;
                if (n < N) {
                    float v = o[j];
                    if (addC) v += Cin[off + j];
                    C[off + j] = v;
                }
            }
        }
    }
}

// ================= small kernels =================
__global__ void pe_kernel(float* __restrict__ pe) {
    int idx = blockIdx.x * 256 + threadIdx.x;
    if (idx >= HW * DD) return;
    int p = idx >> 9, c = idx & 511;
    float pos = (float)(p + 1);
    int j = c & 255;
    float f = powf(10000.0f, -(float)j * (1.0f / 256.0f));
    float a = pos * f;
    pe[idx] = (c < 256) ? sinf(a) : cosf(a);
}

__global__ void label_kernel(const float* __restrict__ lab, float* __restrict__ out) {
    int idx = blockIdx.x * 256 + threadIdx.x;
    if (idx >= 3 * BB * HW) return;
    int p = idx % HW;
    int t = idx / HW;
    int b = t % BB;
    int ni = t / BB;
    out[(size_t)b * LE + ni * HW + p] = lab[idx];
}

__global__ void build_kernel(const float* __restrict__ fa, const float* __restrict__ fb,
                             int split, const float* __restrict__ pe,
                             float* __restrict__ xout, int mode) {
    int g = blockIdx.x;
    int img = g >> 4, b = g & 15;
    const float* f = (img < split) ? (fa + (size_t)img * BB * DD * HW)
                                   : (fb + (size_t)(img - split) * BB * DD * HW);
    int p0 = blockIdx.y * 32, c0 = blockIdx.z * 32;
    __shared__ float tl[32][33];
    int tx = threadIdx.x, ty = threadIdx.y;
#pragma unroll
    for (int r = 0; r < 4; r++) {
        int c = c0 + ty + r * 8, p = p0 + tx;
        if (p < HW) tl[ty + r * 8][tx] = f[((size_t)b * DD + c) * HW + p];
    }
    __syncthreads();
#pragma unroll
    for (int r = 0; r < 4; r++) {
        int p = p0 + ty + r * 8, c = c0 + tx;
        if (p < HW) {
            size_t row = (mode == 0) ? ((size_t)b * LE + (size_t)img * HW + p)
                                     : ((size_t)g * LDQ + p);
            xout[row * DD + c] = tl[tx][ty + r * 8] + pe[(size_t)p * DD + c] * 1e-3f;
        }
    }
}

// bias + row L2-normalize (rows of 128)
__global__ void norm_kernel(const float* __restrict__ T, const float* __restrict__ BK,
                            float* __restrict__ O) {
    int row = blockIdx.x, t = threadIdx.x;
    float v = T[(size_t)row * 128 + t] + BK[t];
    float ss = v * v;
#pragma unroll
    for (int m = 16; m; m >>= 1) ss += __shfl_xor_sync(0xffffffffu, ss, m);
    __shared__ float red[4];
    if ((t & 31) == 0) red[t >> 5] = ss;
    __syncthreads();
    float tot = red[0] + red[1] + red[2] + red[3];
    O[(size_t)row * 128 + t] = v / fmaxf(sqrtf(tot), 1e-12f);
}

// softmax per row (no max pass: logits in [-30,30]); optional label fold + mask
__global__ void softmax_kernel(float* __restrict__ P, const float* __restrict__ LABEL,
                               float* __restrict__ MASKOUT, int Lq, int Lk, int ld,
                               int gkMod) {
    int q = blockIdx.x, g = blockIdx.y;
    float* p = P + ((size_t)g * Lq + q) * ld;
    int t = threadIdx.x;
    float vals[6];
    int cnt = 0;
    float sum = 0.0f;
    for (int i = t; i < Lk; i += 256) {
        float e = __expf(p[i]);
        vals[cnt++] = e;
        sum += e;
    }
    __shared__ float red[8];
#pragma unroll
    for (int m = 16; m; m >>= 1) sum += __shfl_xor_sync(0xffffffffu, sum, m);
    if ((t & 31) == 0) red[t >> 5] = sum;
    __syncthreads();
    float tot = 0.0f;
#pragma unroll
    for (int i = 0; i < 8; i++) tot += red[i];
    float rinv = 1.0f / tot;
    if (LABEL) {
        const float* lb = LABEL + (size_t)(gkMod ? (g & 15) : g) * Lk;
        float ms = 0.0f;
        cnt = 0;
        for (int i = t; i < Lk; i += 256) {
            float pv = vals[cnt] * rinv * lb[i];
            vals[cnt++] = pv;
            ms += pv;
        }
        __syncthreads();
#pragma unroll
        for (int m = 16; m; m >>= 1) ms += __shfl_xor_sync(0xffffffffu, ms, m);
        if ((t & 31) == 0) red[t >> 5] = ms;
        __syncthreads();
        if (t == 0) {
            float mt = 0.0f;
#pragma unroll
            for (int i = 0; i < 8; i++) mt += red[i];
            MASKOUT[(size_t)g * Lq + q] = mt;
        }
        cnt = 0;
        for (int i = t; i < ld; i += 256) p[i] = (i < Lk) ? vals[cnt++] : 0.0f;
    } else {
        cnt = 0;
        for (int i = t; i < ld; i += 256) p[i] = (i < Lk) ? vals[cnt++] * rinv : 0.0f;
    }
}

// InstanceL2Norm: partial sums then apply (deterministic 2-stage)
__global__ void inorm_part(const float* __restrict__ in, float* __restrict__ part) {
    int g = blockIdx.x, q = blockIdx.y, t = threadIdx.x;
    const float4* ip = (const float4*)(in + (size_t)g * GRP) + (size_t)q * QF4;
    float ss = 0.0f;
    for (int i = t; i < QF4; i += 256) {
        float4 v = ip[i];
        ss += v.x * v.x + v.y * v.y + v.z * v.z + v.w * v.w;
    }
    __shared__ float red[8];
#pragma unroll
    for (int m = 16; m; m >>= 1) ss += __shfl_xor_sync(0xffffffffu, ss, m);
    if ((t & 31) == 0) red[t >> 5] = ss;
    __syncthreads();
    if (t == 0) {
        float s = 0.0f;
#pragma unroll
        for (int i = 0; i < 8; i++) s += red[i];
        part[g * 4 + q] = s;
    }
}

__global__ void inorm_apply(const float* __restrict__ in, float* __restrict__ out,
                            const float* __restrict__ part) {
    int g = blockIdx.x, q = blockIdx.y, t = threadIdx.x;
    float ss = part[g * 4 + 0] + part[g * 4 + 1] + part[g * 4 + 2] + part[g * 4 + 3];
    float sc = NSCALE * sqrtf(DHWF / (ss + IEPS));
    const float4* ip = (const float4*)(in + (size_t)g * GRP) + (size_t)q * QF4;
    float4* op = (float4*)(out + (size_t)g * GRP) + (size_t)q * QF4;
    for (int i = t; i < QF4; i += 256) {
        float4 v = ip[i];
        v.x *= sc; v.y *= sc; v.z *= sc; v.w *= sc;
        op[i] = v;
    }
}

// decoder 3-sum partials: u = x*mask, v = x + t3
__global__ void dec_part_kernel(const float* __restrict__ X, const float* __restrict__ XP,
                                const float* __restrict__ MASK, float* __restrict__ part) {
    int g = blockIdx.x, q = blockIdx.y, t = threadIdx.x;
    const float4* x4 = (const float4*)(X + (size_t)g * GRP);
    const float4* p4 = (const float4*)(XP + (size_t)g * GRP);
    const float* mk = MASK + (size_t)g * LDQ;
    float s2 = 0.0f, s4 = 0.0f, cr = 0.0f;
    for (int i = t; i < QF4; i += 256) {
        int gi = q * QF4 + i;
        float m = mk[gi >> 7];
        float4 x = x4[gi];
        float4 v = p4[gi];
        float ux = x.x * m, uy = x.y * m, uz = x.z * m, uw = x.w * m;
        s2 += ux * ux + uy * uy + uz * uz + uw * uw;
        s4 += v.x * v.x + v.y * v.y + v.z * v.z + v.w * v.w;
        cr += ux * v.x + uy * v.y + uz * v.z + uw * v.w;
    }
    __shared__ float r2[8], r4[8], rc[8];
#pragma unroll
    for (int m = 16; m; m >>= 1) {
        s2 += __shfl_xor_sync(0xffffffffu, s2, m);
        s4 += __shfl_xor_sync(0xffffffffu, s4, m);
        cr += __shfl_xor_sync(0xffffffffu, cr, m);
    }
    if ((t & 31) == 0) { r2[t >> 5] = s2; r4[t >> 5] = s4; rc[t >> 5] = cr; }
    __syncthreads();
    if (t == 0) {
        float a = 0, b = 0, c = 0;
#pragma unroll
        for (int i = 0; i < 8; i++) { a += r2[i]; b += r4[i]; c += rc[i]; }
        part[(g * 4 + q) * 3 + 0] = a;
        part[(g * 4 + q) * 3 + 1] = b;
        part[(g * 4 + q) * 3 + 2] = c;
    }
}

__global__ void dec_scale_kernel(const float* __restrict__ part, float* __restrict__ SC) {
    int g = threadIdx.x;
    if (g >= 96) return;
    float a = 0, b = 0, c = 0;
#pragma unroll
    for (int q = 0; q < 4; q++) {
        a += part[(g * 4 + q) * 3 + 0];
        b += part[(g * 4 + q) * 3 + 1];
        c += part[(g * 4 + q) * 3 + 2];
    }
    float S2 = NSCALE * sqrtf(DHWF / (a + IEPS));
    float S4 = NSCALE * sqrtf(DHWF / (b + IEPS));
    float sso = S2 * S2 * a + 2.0f * S2 * S4 * c + S4 * S4 * b;
    float SO = NSCALE * sqrtf(DHWF / (sso + IEPS));
    SC[g * 4 + 0] = S2;
    SC[g * 4 + 1] = S4;
    SC[g * 4 + 2] = SO;
}

__global__ void final_kernel(const float* __restrict__ X, const float* __restrict__ XP,
                             const float* __restrict__ MASK, const float* __restrict__ SC,
                             float* __restrict__ out) {
    int g = blockIdx.x;
    float S2 = SC[g * 4 + 0], S4 = SC[g * 4 + 1], SO = SC[g * 4 + 2];
    int p0 = blockIdx.y * 32, c0 = blockIdx.z * 32;
    __shared__ float tile[32][33];
    int tx = threadIdx.x, ty = threadIdx.y;
    size_t base = (size_t)g * GRP;
#pragma unroll
    for (int r = 0; r < 4; r++) {
        int p = p0 + ty + r * 8, c = c0 + tx;
        if (p < LDQ) {
            size_t idx = base + (size_t)p * 512 + c;
            float u = X[idx] * MASK[(size_t)g * LDQ + p];
            tile[ty + r * 8][tx] = SO * (S2 * u + S4 * XP[idx]);
        }
    }
    __syncthreads();
#pragma unroll
    for (int r = 0; r < 4; r++) {
        int p = p0 + tx, c = c0 + ty + r * 8;
        if (p < LDQ) out[((size_t)g * 512 + c) * LDQ + p] = tile[tx][ty + r * 8];
    }
}

// ================= launcher =================
static void gemm_launch(int transB, const float* A, const float* B, const float* Cin,
                        float* C, int M, int N, int Kloop, int KB,
                        int ldA, int ldB, int ldC, size_t sA, size_t sB, size_t sC,
                        int gkMod, float alpha, int addC, int G) {
    dim3 grid((N + 127) / 128, (M + 127) / 128, G);
    if (transB)
        gemm_kernel<1><<<grid, 256>>>(A, B, Cin, C, M, N, Kloop, KB, ldA, ldB, ldC,
                                      sA, sB, sC, gkMod, alpha, addC);
    else
        gemm_kernel<0><<<grid, 256>>>(A, B, Cin, C, M, N, Kloop, KB, ldA, ldB, ldC,
                                      sA, sB, sC, gkMod, alpha, addC);
}

extern "C" void kernel_launch(void* const* d_in, const int* in_sizes, int n_in,
                              void* d_out, int out_size) {
    const float* train_feat  = (const float*)d_in[0];
    const float* test_feat   = (const float*)d_in[1];
    const float* train_label = (const float*)d_in[2];
    const float* wk_self     = (const float*)d_in[3];
    const float* bk_self     = (const float*)d_in[4];
    const float* wk_cross    = (const float*)d_in[5];
    const float* bk_cross    = (const float*)d_in[6];
    float* out = (float*)d_out;

    float* base = nullptr;
    cudaGetSymbolAddress((void**)&base, g_scratch);
    float* pe    = base + OFF_PE;
    float* label = base + OFF_LABEL;
    float* xe    = base + OFF_XE;
    float* x1e   = base + OFF_X1E;
    float* mem   = base + OFF_MEM;
    float* pq    = base + OFF_PQ;
    float* pkc   = base + OFF_PKC;
    float* dx0   = base + OFF_DX0;
    float* dx1   = base + OFF_DX1;
    float* dx    = base + OFF_DX;
    float* dxpt3 = base + OFF_DXPT3;
    float* dpq   = base + OFF_DPQ;
    float* dmask = base + OFF_DMASK;
    float* dsc   = base + OFF_DSC;
    float* ipart = base + OFF_IPART;
    float* dpart = base + OFF_DPART;
    float* probs = base + OFF_PROBS;

    dim3 tb(32, 8);

    pe_kernel<<<(HW * DD + 255) / 256, 256>>>(pe);
    label_kernel<<<(3 * BB * HW + 255) / 256, 256>>>(train_label, label);

    // ---- encoder ----
    build_kernel<<<dim3(48, 16, 16), tb>>>(train_feat, train_feat, 3, pe, xe, 0);
    // proj self (tmp in probs) -> pq
    gemm_launch(1, xe, wk_self, nullptr, probs, LE, 128, 512, 512, 512, 512, 128,
                (size_t)LE * 512, 0, (size_t)LE * 128, 0, 1.0f, 0, 16);
    norm_kernel<<<16 * LE, 128>>>(probs, bk_self, pq);
    // logits
    gemm_launch(1, pq, pq, nullptr, probs, LE, LE, 128, 128, 128, 128, 1456,
                (size_t)LE * 128, (size_t)LE * 128, (size_t)LE * 1456, 0, 30.0f, 0, 16);
    softmax_kernel<<<dim3(LE, 16), 256>>>(probs, nullptr, nullptr, LE, LE, 1456, 0);
    // value + residual
    gemm_launch(0, probs, xe, xe, x1e, LE, 512, 1456, LE, 1456, 512, 512,
                (size_t)LE * 1456, (size_t)LE * 512, (size_t)LE * 512, 0, 1.0f, 1, 16);
    inorm_part<<<dim3(48, 4), 256>>>(x1e, ipart);
    inorm_apply<<<dim3(48, 4), 256>>>(x1e, mem, ipart);
    // cross keys
    gemm_launch(1, mem, wk_cross, nullptr, probs, LE, 128, 512, 512, 512, 512, 128,
                (size_t)LE * 512, 0, (size_t)LE * 128, 0, 1.0f, 0, 16);
    norm_kernel<<<16 * LE, 128>>>(probs, bk_cross, pkc);

    // ---- decoder (96 batched) ----
    build_kernel<<<dim3(96, 16, 16), tb>>>(train_feat, test_feat, 3, pe, dx0, 1);
    gemm_launch(1, dx0, wk_self, nullptr, probs, LDQ, 128, 512, 512, 512, 512, 128,
                (size_t)LDQ * 512, 0, (size_t)LDQ * 128, 0, 1.0f, 0, 96);
    norm_kernel<<<96 * LDQ, 128>>>(probs, bk_self, dpq);
    gemm_launch(1, dpq, dpq, nullptr, probs, LDQ, LDQ, 128, 128, 128, 128, 496,
                (size_t)LDQ * 128, (size_t)LDQ * 128, (size_t)LDQ * 496, 0, 30.0f, 0, 96);
    softmax_kernel<<<dim3(LDQ, 96), 256>>>(probs, nullptr, nullptr, LDQ, LDQ, 496, 0);
    gemm_launch(0, probs, dx0, dx0, dx1, LDQ, 512, 496, LDQ, 496, 512, 512,
                (size_t)LDQ * 496, (size_t)LDQ * 512, (size_t)LDQ * 512, 0, 1.0f, 1, 96);
    inorm_part<<<dim3(96, 4), 256>>>(dx1, ipart);
    inorm_apply<<<dim3(96, 4), 256>>>(dx1, dx, ipart);
    gemm_launch(1, dx, wk_cross, nullptr, probs, LDQ, 128, 512, 512, 512, 512, 128,
                (size_t)LDQ * 512, 0, (size_t)LDQ * 128, 0, 1.0f, 0, 96);
    norm_kernel<<<96 * LDQ, 128>>>(probs, bk_cross, dpq);
    // cross logits vs pkc (shared per batch: gk = g & 15)
    gemm_launch(1, dpq, pkc, nullptr, probs, LDQ, LE, 128, 128, 128, 128, 1456,
                (size_t)LDQ * 128, (size_t)LE * 128, (size_t)LDQ * 1456, 1, 30.0f, 0, 96);
    softmax_kernel<<<dim3(LDQ, 96), 256>>>(probs, label, dmask, LDQ, LE, 1456, 1);
    gemm_launch(0, probs, mem, dx, dxpt3, LDQ, 512, 1456, LE, 1456, 512, 512,
                (size_t)LDQ * 1456, (size_t)LE * 512, (size_t)LDQ * 512, 1, 1.0f, 1, 96);
    dec_part_kernel<<<dim3(96, 4), 256>>>(dx, dxpt3, dmask, dpart);
    dec_scale_kernel<<<1, 96>>>(dpart, dsc);
    final_kernel<<<dim3(96, 16, 16), tb>>>(dx, dxpt3, dmask, dsc, out);
}